// round 15
// baseline (speedup 1.0000x reference)
#include <cuda_runtime.h>
#include <cuda_fp16.h>
#include <cstdint>

// ---------------------------------------------------------------- constants
#define B_    64
#define C_    32
#define V_    512
#define L_    13
#define COUT  64
#define M_ROWS 26624            // B_*C_*L_  GEMM1 rows ordered (n,l,c)
#define NB    3072              // 6 support-powers * 512
#define KA    512               // A cols: xh only
#define KB    512               // B cols: ah only
#define ZROWS 425984            // 64 n * 6656 (w,l)  — zT rows ordered (n,w,l)
#define ZTC   224               // zT cols: hi only (7 chan blocks x 32)
#define VL    6656              // 512*13

// ---------------------------------------------------------------- scratch
__device__ __half g_Ah[(size_t)M_ROWS * KA];      // 27.3 MB
__device__ __half g_Bh[(size_t)NB * KB];          // 3.1 MB
__device__ __half g_zT[(size_t)ZROWS * ZTC];      // 190.8 MB
__device__ __half g_Wh[COUT * 224];
__device__ float  g_pow[3 * V_ * V_];

// ---------------------------------------------------------------- utils
__device__ __forceinline__ uint32_t smem_u32(const void* p) {
    uint32_t a;
    asm("{ .reg .u64 t; cvta.to.shared.u64 t, %1; cvt.u32.u64 %0, t; }" : "=r"(a) : "l"(p));
    return a;
}
__device__ __forceinline__ void cp_async16(uint32_t s, const void* g) {
    asm volatile("cp.async.cg.shared.global [%0], [%1], 16;" :: "r"(s), "l"(g));
}
__device__ __forceinline__ void ldsm4(uint32_t* r, uint32_t addr) {
    asm volatile("ldmatrix.sync.aligned.m8n8.x4.shared.b16 {%0,%1,%2,%3}, [%4];"
                 : "=r"(r[0]), "=r"(r[1]), "=r"(r[2]), "=r"(r[3]) : "r"(addr));
}
__device__ __forceinline__ void mma16816(float* d, const uint32_t* a, uint32_t b0, uint32_t b1) {
    asm volatile(
        "mma.sync.aligned.m16n8k16.row.col.f32.f16.f16.f32 "
        "{%0,%1,%2,%3}, {%4,%5,%6,%7}, {%8,%9}, {%0,%1,%2,%3};"
        : "+f"(d[0]), "+f"(d[1]), "+f"(d[2]), "+f"(d[3])
        : "r"(a[0]), "r"(a[1]), "r"(a[2]), "r"(a[3]), "r"(b0), "r"(b1));
}
#define SW128(off) ((off) ^ (((off) >> 3) & 0x70))

__device__ __forceinline__ uint16_t hbits(float f) {
    __half h = __float2half_rn(f);
    return *reinterpret_cast<uint16_t*>(&h);
}

// ---------------------------------------------------------------- 1) a^2 (fp32)
__global__ __launch_bounds__(256)
void pow_kernel(const float* __restrict__ a0, const float* __restrict__ a1,
                const float* __restrict__ a2, float* __restrict__ out) {
    const float* A = (blockIdx.z == 0) ? a0 : (blockIdx.z == 1 ? a1 : a2);
    float* Cc = out + (size_t)blockIdx.z * V_ * V_;
    __shared__ float As[16][64];
    __shared__ float Bs[16][68];
    const int tid = threadIdx.x;
    const int bm = blockIdx.y * 64, bn = blockIdx.x * 64;
    const int tx = tid & 15, ty = tid >> 4;
    float acc[4][4] = {};
    for (int kb = 0; kb < 512; kb += 16) {
        float4 va = *(const float4*)(A + (size_t)(bm + (tid >> 2)) * 512 + kb + (tid & 3) * 4);
        As[(tid & 3) * 4 + 0][tid >> 2] = va.x;
        As[(tid & 3) * 4 + 1][tid >> 2] = va.y;
        As[(tid & 3) * 4 + 2][tid >> 2] = va.z;
        As[(tid & 3) * 4 + 3][tid >> 2] = va.w;
        *(float4*)&Bs[tid >> 4][(tid & 15) * 4] =
            *(const float4*)(A + (size_t)(kb + (tid >> 4)) * 512 + bn + (tid & 15) * 4);
        __syncthreads();
        #pragma unroll
        for (int k = 0; k < 16; k++) {
            float wf[4], hf[4];
            #pragma unroll
            for (int i = 0; i < 4; i++) wf[i] = As[k][ty * 4 + i];
            #pragma unroll
            for (int j = 0; j < 4; j++) hf[j] = Bs[k][tx * 4 + j];
            #pragma unroll
            for (int i = 0; i < 4; i++)
                #pragma unroll
                for (int j = 0; j < 4; j++) acc[i][j] = fmaf(wf[i], hf[j], acc[i][j]);
        }
        __syncthreads();
    }
    #pragma unroll
    for (int i = 0; i < 4; i++)
        #pragma unroll
        for (int j = 0; j < 4; j++)
            Cc[(size_t)(bm + ty * 4 + i) * 512 + bn + tx * 4 + j] = acc[i][j];
}

// ---------------------------------------------------------------- 2) A rows (n,l,c): xh (u32 stores)
__global__ __launch_bounds__(256)
void build_A(const float* __restrict__ x, __half* __restrict__ Ah) {
    __shared__ float s[V_ * L_];
    const int nc = blockIdx.x;              // n*32 + c
    const int n = nc >> 5, c = nc & 31;
    const int tid = threadIdx.x;
    const float* slab = x + (size_t)nc * (V_ * L_);
    for (int i = tid; i < V_ * L_; i += 256) s[i] = slab[i];
    __syncthreads();
    for (int e = tid; e < (V_ / 2) * L_; e += 256) {
        int l = e / 256, v2 = (e & 255) * 2;
        float v0 = s[v2 * L_ + l];
        float v1 = s[(v2 + 1) * L_ + l];
        uint32_t pk = (uint32_t)hbits(v0) | ((uint32_t)hbits(v1) << 16);
        size_t m = ((size_t)n * L_ + l) * 32 + c;
        *(uint32_t*)((uint16_t*)Ah + m * KA + v2) = pk;
    }
}

// ---------------------------------------------------------------- 3) B (hi only)
__global__ __launch_bounds__(256)
void build_B(const float* __restrict__ a0, const float* __restrict__ a1,
             const float* __restrict__ a2, const float* __restrict__ pw,
             __half* __restrict__ Bh) {
    int idx = blockIdx.x * 256 + threadIdx.x;
    if (idx >= NB * 512) return;
    int v = idx & 511;
    int j = idx >> 9;                // B row: p*512 + w
    int p = j >> 9;
    int w = j & 511;
    const float* P = (p & 1) ? (pw + (size_t)(p >> 1) * V_ * V_)
                             : (p == 0 ? a0 : (p == 2 ? a1 : a2));
    ((uint16_t*)Bh)[(size_t)j * KB + v] = hbits(P[(size_t)v * 512 + w]);
}

// ---------------------------------------------------------------- 4) seed zT block 0 (x hi), rows (n,w,l)
__global__ __launch_bounds__(512)
void seed_zT(const __half* __restrict__ Ah, __half* __restrict__ zT) {
    __shared__ uint32_t s32[32 * 257];      // [c][256 u32], pitch 257
    const int nl = blockIdx.x;              // n*13 + l
    const int n = nl / 13, l = nl - n * 13;
    const int tid = threadIdx.x;
    for (int i = tid; i < 32 * 256; i += 512) {
        int c = i >> 8, kk = i & 255;
        const uint32_t* pa = (const uint32_t*)(Ah + ((size_t)nl * 32 + c) * KA);
        s32[c * 257 + kk] = pa[kk];
    }
    __syncthreads();
    const int v = tid;
    uint32_t hi[16];
    #pragma unroll
    for (int i = 0; i < 16; i++) {
        uint32_t w0 = s32[(2*i) * 257 + (v >> 1)];
        uint32_t w1 = s32[(2*i+1) * 257 + (v >> 1)];
        uint16_t h0 = (v & 1) ? (uint16_t)(w0 >> 16) : (uint16_t)w0;
        uint16_t h1 = (v & 1) ? (uint16_t)(w1 >> 16) : (uint16_t)w1;
        hi[i] = (uint32_t)h0 | ((uint32_t)h1 << 16);
    }
    size_t gr = ((size_t)n * V_ + v) * L_ + l;      // row (n,v,l)
    char* dst = (char*)zT + gr * (ZTC * 2);
    #pragma unroll
    for (int i = 0; i < 4; i++)
        *(uint4*)(dst + i * 16) = *(uint4*)(hi + i * 4);
}

// ---------------------------------------------------------------- 5) GEMM1 (HMMA fp16), BM=256 x BN=128, 512 thr, 4x4 warps
#define BMg 256
#define BNg 128
#define BKg 64
#define NSTG 3
#define STG_A (BMg * BKg * 2)              // 32768
#define STG_B (BNg * BKg * 2)              // 16384
#define STG_BYTES (STG_A + STG_B)          // 49152
#define GEMM_SMEM (NSTG * STG_BYTES)       // 147456 (epilogue [256][129] fp32 = 132096 fits)
#define KITERS 8                            // KA/BKg

__global__ __launch_bounds__(512, 1)
void mma_gemm(const __half* __restrict__ A, const __half* __restrict__ Bm,
              __half* __restrict__ zT) {
    extern __shared__ char smem[];
    const uint32_t sb = smem_u32(smem);
    const int tid = threadIdx.x;
    const int wid = tid >> 5, lane = tid & 31;
    const int bm = blockIdx.y * BMg;       // N-fastest launch for A L2 reuse
    const int bn = blockIdx.x * BNg;
    const int wm = wid & 3;                // 4 M slices of 64 rows
    const int wn = wid >> 2;               // 4 N slices of 32 cols

    float acc[4][4][4];                    // [mf][nq*2+h][4]
    #pragma unroll
    for (int i = 0; i < 4; i++)
        #pragma unroll
        for (int j = 0; j < 4; j++)
            #pragma unroll
            for (int q = 0; q < 4; q++) acc[i][j][q] = 0.f;

    auto load_stage = [&](int slot, int it) {
        const uint32_t abase = sb + slot * STG_BYTES;
        const uint32_t bbase = abase + STG_A;
        const __half* Ag = A + (size_t)bm * KA + it * BKg;
        const __half* Bg = Bm + (size_t)bn * KB + it * BKg;
        #pragma unroll
        for (int i = 0; i < 4; i++) {              // A: 2048 x 16B
            int c = tid + i * 512;
            int row = c >> 3, c16 = c & 7;
            uint32_t off = (uint32_t)(row * 128 + c16 * 16);
            cp_async16(abase + SW128(off), Ag + (size_t)row * KA + c16 * 8);
        }
        #pragma unroll
        for (int i = 0; i < 2; i++) {              // B: 1024 x 16B
            int c = tid + i * 512;
            int row = c >> 3, c16 = c & 7;
            uint32_t off = (uint32_t)(row * 128 + c16 * 16);
            cp_async16(bbase + SW128(off), Bg + (size_t)row * KB + c16 * 8);
        }
        asm volatile("cp.async.commit_group;" ::: "memory");
    };

    load_stage(0, 0);
    load_stage(1, 1);

    for (int it = 0; it < KITERS; it++) {
        if (it < KITERS - 1) asm volatile("cp.async.wait_group 1;" ::: "memory");
        else                 asm volatile("cp.async.wait_group 0;" ::: "memory");
        __syncthreads();
        if (it + 2 < KITERS) load_stage((it + 2) % NSTG, it + 2);

        const uint32_t abase = sb + (it % NSTG) * STG_BYTES;
        const uint32_t bbase = abase + STG_A;
        const int lrow = lane & 15;
        const int lkh  = (lane >> 4) << 3;

        #pragma unroll
        for (int ks = 0; ks < 4; ks++) {
            const int k0 = ks * 16;
            uint32_t a_regs[4][4];
            #pragma unroll
            for (int mf = 0; mf < 4; mf++) {
                int row = wm * 64 + mf * 16 + lrow;
                ldsm4(a_regs[mf], abase + SW128((uint32_t)(row * 128 + (k0 + lkh) * 2)));
            }
            #pragma unroll
            for (int nq = 0; nq < 2; nq++) {
                uint32_t b_regs[4];
                int row = wn * 32 + nq * 16 + lrow;
                ldsm4(b_regs, bbase + SW128((uint32_t)(row * 128 + (k0 + lkh) * 2)));
                #pragma unroll
                for (int mf = 0; mf < 4; mf++) {
                    mma16816(acc[mf][nq * 2 + 0], a_regs[mf], b_regs[0], b_regs[2]);
                    mma16816(acc[mf][nq * 2 + 1], a_regs[mf], b_regs[1], b_regs[3]);
                }
            }
        }
    }
    __syncthreads();    // smem reuse below

    // epilogue: acc -> smem fp32 [256][129] -> zT fp16 hi, c-transposed, rows (n,w,l)
    float* s = (float*)smem;
    const int gid = lane >> 2, tig = lane & 3;
    #pragma unroll
    for (int mf = 0; mf < 4; mf++) {
        int r0 = wm * 64 + mf * 16 + gid;
        #pragma unroll
        for (int nf = 0; nf < 4; nf++) {
            int cc = wn * 32 + nf * 8 + tig * 2;
            float* d = acc[mf][nf];
            s[r0 * 129 + cc] = d[0];       s[r0 * 129 + cc + 1] = d[1];
            s[(r0 + 8) * 129 + cc] = d[2]; s[(r0 + 8) * 129 + cc + 1] = d[3];
        }
    }
    __syncthreads();

    const int p = bn >> 9;
    const int wbase = bn & 511;
    const int nlbase = bm >> 5;             // first of 8 (n,l) groups
    #pragma unroll
    for (int rep = 0; rep < 2; rep++) {
        int rw = tid + rep * 512;           // 1024 = 8 nlg x 128 w
        int nlg = rw >> 7, w = rw & 127;
        uint32_t hi[16];
        #pragma unroll
        for (int i = 0; i < 16; i++) {
            float v0 = s[(nlg * 32 + 2*i) * 129 + w];
            float v1 = s[(nlg * 32 + 2*i + 1) * 129 + w];
            hi[i] = (uint32_t)hbits(v0) | ((uint32_t)hbits(v1) << 16);
        }
        int nl = nlbase + nlg;
        int n = nl / 13, l = nl - n * 13;
        size_t gr = ((size_t)n * V_ + wbase + w) * L_ + l;
        char* dst = (char*)zT + gr * (ZTC * 2) + (p + 1) * 64;
        #pragma unroll
        for (int i = 0; i < 4; i++)
            *(uint4*)(dst + i * 16) = *(uint4*)(hi + i * 4);
    }
}

// ---------------------------------------------------------------- 6) W fp32 -> fp16
__global__ __launch_bounds__(256)
void build_W(const float* __restrict__ W, __half* __restrict__ Wh) {
    int idx = blockIdx.x * 256 + threadIdx.x;
    if (idx >= COUT * 224) return;
    ((uint16_t*)Wh)[idx] = hbits(W[idx]);
}

// ---------------------------------------------------------------- 7) mix GEMM (HMMA fp16), BM=256, fused output
#define MIX_BM 256
#define MIX_WP 232                          // ws pitch (u16)
#define MIX_WBYTES (COUT * MIX_WP * 2)      // 29696
#define MIX_APITCH 80
#define MIX_ASTAGE (MIX_BM * MIX_APITCH)    // 20480
#define MIX_S2 (COUT * 260 * 4)             // 66560 epilogue buffer
#define MIX_SMEM (MIX_WBYTES + MIX_S2)      // 96256 (>= WBYTES + 3*ASTAGE = 91136)

__global__ __launch_bounds__(256, 2)
void mix_gemm(const __half* __restrict__ zT, const __half* __restrict__ Wh,
              const float* __restrict__ bias, float* __restrict__ out) {
    extern __shared__ char smem[];
    const uint32_t sb = smem_u32(smem);
    uint16_t* ws = (uint16_t*)smem;                        // [64][232]
    const uint32_t asb = sb + MIX_WBYTES;
    const int tid = threadIdx.x;
    const int wid = tid >> 5, lane = tid & 31;
    const int bm = blockIdx.x * MIX_BM;                    // 1664 tiles; 26 per n
    const int wm = wid & 3, wn = wid >> 2;                 // warp tile 64 rows x 32 cols

    for (int i = tid; i < COUT * 112; i += 256) {
        int o = i / 112, kk = (i % 112) * 2;
        *(uint32_t*)(ws + o * MIX_WP + kk) =
            *(const uint32_t*)((const uint16_t*)Wh + o * 224 + kk);
    }

    float acc[4][4][4];
    #pragma unroll
    for (int i = 0; i < 4; i++)
        #pragma unroll
        for (int j = 0; j < 4; j++)
            #pragma unroll
            for (int q = 0; q < 4; q++) acc[i][j][q] = 0.f;

    auto load_stage = [&](int slot, int chunk) {
        const uint32_t base = asb + slot * MIX_ASTAGE;
        const int ac = chunk * 32;
        #pragma unroll
        for (int i = 0; i < 4; i++) {                      // 1024 x 16B
            int c = tid + i * 256;
            int row = c >> 2, c16 = c & 3;
            cp_async16(base + row * MIX_APITCH + c16 * 16,
                       zT + ((size_t)bm + row) * ZTC + ac + c16 * 8);
        }
        asm volatile("cp.async.commit_group;" ::: "memory");
    };

    load_stage(0, 0);
    load_stage(1, 1);
    __syncthreads();    // covers ws preload too

    const int lrow = lane & 15;
    const int lkh  = (lane >> 4) << 3;
    const int og   = lane >> 2;
    const int kq   = (lane & 3) * 2;

    for (int it = 0; it < 7; it++) {
        if (it < 6) asm volatile("cp.async.wait_group 1;" ::: "memory");
        else        asm volatile("cp.async.wait_group 0;" ::: "memory");
        __syncthreads();
        if (it + 2 < 7) load_stage((it + 2) % 3, it + 2);

        const uint32_t abase = asb + (it % 3) * MIX_ASTAGE;
        const int bc = it * 32;

        #pragma unroll
        for (int ks = 0; ks < 2; ks++) {
            uint32_t a_regs[4][4];
            #pragma unroll
            for (int mf = 0; mf < 4; mf++) {
                int row = wm * 64 + mf * 16 + lrow;
                ldsm4(a_regs[mf], abase + row * MIX_APITCH + (ks * 16 + lkh) * 2);
            }
            #pragma unroll
            for (int nq = 0; nq < 4; nq++) {
                int o = wn * 32 + nq * 8 + og;
                int k = bc + ks * 16 + kq;
                uint32_t b0 = *(uint32_t*)(ws + o * MIX_WP + k);
                uint32_t b1 = *(uint32_t*)(ws + o * MIX_WP + k + 8);
                #pragma unroll
                for (int mf = 0; mf < 4; mf++)
                    mma16816(acc[mf][nq], a_regs[mf], b0, b1);
            }
        }
    }
    __syncthreads();    // smem reuse as s2

    // epilogue: stage [o][row] (pitch 260), then coalesced direct out writes
    float* s2 = (float*)(smem + MIX_WBYTES);
    const int gid = lane >> 2, tig = lane & 3;
    #pragma unroll
    for (int mf = 0; mf < 4; mf++) {
        int r0 = wm * 64 + mf * 16 + gid;
        #pragma unroll
        for (int nq = 0; nq < 4; nq++) {
            int o = wn * 32 + nq * 8 + tig * 2;
            float* d = acc[mf][nq];
            s2[o * 260 + r0] = d[0];       s2[(o + 1) * 260 + r0] = d[1];
            s2[o * 260 + r0 + 8] = d[2];   s2[(o + 1) * 260 + r0 + 8] = d[3];
        }
    }
    __syncthreads();

    // rows = contiguous (w,l) span within one n (6656 = 26*256)
    const int n = bm / VL;
    const int rowbase = bm - n * VL;
    #pragma unroll
    for (int i = 0; i < 16; i++) {
        int idx = tid + i * 256;           // 4096 float4s = 64 o x 256 floats
        int o = idx >> 6, q = idx & 63;
        float4 v = *(float4*)(s2 + o * 260 + q * 4);
        float bo = bias[o];
        v.x += bo; v.y += bo; v.z += bo; v.w += bo;
        *(float4*)(out + ((size_t)n * COUT + o) * VL + rowbase + q * 4) = v;
    }
}

// ---------------------------------------------------------------- launcher (R12 multi-stream DAG)
extern "C" void kernel_launch(void* const* d_in, const int* in_sizes, int n_in,
                              void* d_out, int out_size) {
    const float* x  = (const float*)d_in[0];
    const float* a0 = (const float*)d_in[1];
    const float* a1 = (const float*)d_in[2];
    const float* a2 = (const float*)d_in[3];
    const float* W  = (const float*)d_in[4];
    const float* b  = (const float*)d_in[5];
    float* out = (float*)d_out;

    float* pw;
    __half *Ah, *Bh, *zT, *Wh;
    cudaGetSymbolAddress((void**)&pw,  g_pow);
    cudaGetSymbolAddress((void**)&Ah,  g_Ah);
    cudaGetSymbolAddress((void**)&Bh,  g_Bh);
    cudaGetSymbolAddress((void**)&zT,  g_zT);
    cudaGetSymbolAddress((void**)&Wh,  g_Wh);

    cudaFuncSetAttribute(mma_gemm, cudaFuncAttributeMaxDynamicSharedMemorySize, GEMM_SMEM);
    cudaFuncSetAttribute(mix_gemm, cudaFuncAttributeMaxDynamicSharedMemorySize, MIX_SMEM);

    // Host-side stream/event objects, created once (no device memory involved).
    static cudaStream_t s2 = nullptr, s3 = nullptr;
    static cudaEvent_t evRoot = nullptr, evA = nullptr, evB = nullptr,
                       evS = nullptr, evW = nullptr;
    if (s2 == nullptr) {
        cudaStreamCreateWithFlags(&s2, cudaStreamNonBlocking);
        cudaStreamCreateWithFlags(&s3, cudaStreamNonBlocking);
        cudaEventCreateWithFlags(&evRoot, cudaEventDisableTiming);
        cudaEventCreateWithFlags(&evA, cudaEventDisableTiming);
        cudaEventCreateWithFlags(&evB, cudaEventDisableTiming);
        cudaEventCreateWithFlags(&evS, cudaEventDisableTiming);
        cudaEventCreateWithFlags(&evW, cudaEventDisableTiming);
    }

    // fork
    cudaEventRecord(evRoot, 0);
    cudaStreamWaitEvent(s2, evRoot, 0);
    cudaStreamWaitEvent(s3, evRoot, 0);

    // side branch s2: supports -> a^2 -> Bh, plus Wh
    pow_kernel<<<dim3(8, 8, 3), 256, 0, s2>>>(a0, a1, a2, pw);
    build_B<<<(NB * 512) / 256, 256, 0, s2>>>(a0, a1, a2, pw, Bh);
    cudaEventRecord(evB, s2);
    build_W<<<(COUT * 224 + 255) / 256, 256, 0, s2>>>(W, Wh);
    cudaEventRecord(evW, s2);

    // main stream: x -> Ah
    build_A<<<B_ * C_, 256>>>(x, Ah);
    cudaEventRecord(evA, 0);

    // side branch s3: seed zT block 0 (runs concurrently with GEMM1)
    cudaStreamWaitEvent(s3, evA, 0);
    seed_zT<<<B_ * L_, 512, 0, s3>>>(Ah, zT);
    cudaEventRecord(evS, s3);

    // main stream: GEMM1 (needs Ah in-stream + Bh via event)
    cudaStreamWaitEvent(0, evB, 0);
    mma_gemm<<<dim3(NB / BNg, M_ROWS / BMg), 512, GEMM_SMEM>>>(Ah, Bh, zT);

    // join: mix needs zT block 0 (seed) + Wh; writes out directly
    cudaStreamWaitEvent(0, evS, 0);
    cudaStreamWaitEvent(0, evW, 0);
    mix_gemm<<<ZROWS / MIX_BM, 256, MIX_SMEM>>>(zT, Wh, b, out);
}

// round 16
// speedup vs baseline: 1.0970x; 1.0970x over previous
#include <cuda_runtime.h>
#include <cuda_fp16.h>
#include <cstdint>

// ---------------------------------------------------------------- constants
#define B_    64
#define C_    32
#define V_    512
#define L_    13
#define COUT  64
#define M_ROWS 26624            // B_*C_*L_  GEMM1 rows ordered (n,l,c)
#define NB    3072              // 6 support-powers * 512
#define KA    512               // A cols: xh only
#define KB    512               // B cols: ah only
#define ZROWS 425984            // 64 n * 6656 (w,l)  — zT rows ordered (n,w,l)
#define ZTC   224               // zT cols: hi only (7 chan blocks x 32)
#define VL    6656              // 512*13

// ---------------------------------------------------------------- scratch
__device__ __half g_Ah[(size_t)M_ROWS * KA];      // 27.3 MB
__device__ __half g_Bh[(size_t)NB * KB];          // 3.1 MB
__device__ __half g_zT[(size_t)ZROWS * ZTC];      // 190.8 MB
__device__ __half g_Wh[COUT * 224];
__device__ float  g_pow[3 * V_ * V_];

// ---------------------------------------------------------------- utils
__device__ __forceinline__ uint32_t smem_u32(const void* p) {
    uint32_t a;
    asm("{ .reg .u64 t; cvta.to.shared.u64 t, %1; cvt.u32.u64 %0, t; }" : "=r"(a) : "l"(p));
    return a;
}
__device__ __forceinline__ void cp_async16(uint32_t s, const void* g) {
    asm volatile("cp.async.cg.shared.global [%0], [%1], 16;" :: "r"(s), "l"(g));
}
__device__ __forceinline__ void ldsm4(uint32_t* r, uint32_t addr) {
    asm volatile("ldmatrix.sync.aligned.m8n8.x4.shared.b16 {%0,%1,%2,%3}, [%4];"
                 : "=r"(r[0]), "=r"(r[1]), "=r"(r[2]), "=r"(r[3]) : "r"(addr));
}
__device__ __forceinline__ void mma16816(float* d, const uint32_t* a, uint32_t b0, uint32_t b1) {
    asm volatile(
        "mma.sync.aligned.m16n8k16.row.col.f32.f16.f16.f32 "
        "{%0,%1,%2,%3}, {%4,%5,%6,%7}, {%8,%9}, {%0,%1,%2,%3};"
        : "+f"(d[0]), "+f"(d[1]), "+f"(d[2]), "+f"(d[3])
        : "r"(a[0]), "r"(a[1]), "r"(a[2]), "r"(a[3]), "r"(b0), "r"(b1));
}
#define SW128(off) ((off) ^ (((off) >> 3) & 0x70))

__device__ __forceinline__ uint16_t hbits(float f) {
    __half h = __float2half_rn(f);
    return *reinterpret_cast<uint16_t*>(&h);
}

// ---------------------------------------------------------------- 1) a^2 (fp32)
__global__ __launch_bounds__(256)
void pow_kernel(const float* __restrict__ a0, const float* __restrict__ a1,
                const float* __restrict__ a2, float* __restrict__ out) {
    const float* A = (blockIdx.z == 0) ? a0 : (blockIdx.z == 1 ? a1 : a2);
    float* Cc = out + (size_t)blockIdx.z * V_ * V_;
    __shared__ float As[16][64];
    __shared__ float Bs[16][68];
    const int tid = threadIdx.x;
    const int bm = blockIdx.y * 64, bn = blockIdx.x * 64;
    const int tx = tid & 15, ty = tid >> 4;
    float acc[4][4] = {};
    for (int kb = 0; kb < 512; kb += 16) {
        float4 va = *(const float4*)(A + (size_t)(bm + (tid >> 2)) * 512 + kb + (tid & 3) * 4);
        As[(tid & 3) * 4 + 0][tid >> 2] = va.x;
        As[(tid & 3) * 4 + 1][tid >> 2] = va.y;
        As[(tid & 3) * 4 + 2][tid >> 2] = va.z;
        As[(tid & 3) * 4 + 3][tid >> 2] = va.w;
        *(float4*)&Bs[tid >> 4][(tid & 15) * 4] =
            *(const float4*)(A + (size_t)(kb + (tid >> 4)) * 512 + bn + (tid & 15) * 4);
        __syncthreads();
        #pragma unroll
        for (int k = 0; k < 16; k++) {
            float wf[4], hf[4];
            #pragma unroll
            for (int i = 0; i < 4; i++) wf[i] = As[k][ty * 4 + i];
            #pragma unroll
            for (int j = 0; j < 4; j++) hf[j] = Bs[k][tx * 4 + j];
            #pragma unroll
            for (int i = 0; i < 4; i++)
                #pragma unroll
                for (int j = 0; j < 4; j++) acc[i][j] = fmaf(wf[i], hf[j], acc[i][j]);
        }
        __syncthreads();
    }
    #pragma unroll
    for (int i = 0; i < 4; i++)
        #pragma unroll
        for (int j = 0; j < 4; j++)
            Cc[(size_t)(bm + ty * 4 + i) * 512 + bn + tx * 4 + j] = acc[i][j];
}

// ---------------------------------------------------------------- 2) A rows (n,l,c): xh (float4 loads, u32 stores)
__global__ __launch_bounds__(256)
void build_A(const float* __restrict__ x, __half* __restrict__ Ah) {
    __shared__ float s[V_ * L_];
    const int nc = blockIdx.x;              // n*32 + c
    const int n = nc >> 5, c = nc & 31;
    const int tid = threadIdx.x;
    const float4* slab4 = (const float4*)(x + (size_t)nc * (V_ * L_));
    for (int i = tid; i < (V_ * L_) / 4; i += 256)
        *(float4*)&s[i * 4] = slab4[i];
    __syncthreads();
    for (int e = tid; e < (V_ / 2) * L_; e += 256) {
        int l = e / 256, v2 = (e & 255) * 2;
        float v0 = s[v2 * L_ + l];
        float v1 = s[(v2 + 1) * L_ + l];
        uint32_t pk = (uint32_t)hbits(v0) | ((uint32_t)hbits(v1) << 16);
        size_t m = ((size_t)n * L_ + l) * 32 + c;
        *(uint32_t*)((uint16_t*)Ah + m * KA + v2) = pk;
    }
}

// ---------------------------------------------------------------- 3) B (hi only)
__global__ __launch_bounds__(256)
void build_B(const float* __restrict__ a0, const float* __restrict__ a1,
             const float* __restrict__ a2, const float* __restrict__ pw,
             __half* __restrict__ Bh) {
    int idx = blockIdx.x * 256 + threadIdx.x;
    if (idx >= NB * 512) return;
    int v = idx & 511;
    int j = idx >> 9;                // B row: p*512 + w
    int p = j >> 9;
    int w = j & 511;
    const float* P = (p & 1) ? (pw + (size_t)(p >> 1) * V_ * V_)
                             : (p == 0 ? a0 : (p == 2 ? a1 : a2));
    ((uint16_t*)Bh)[(size_t)j * KB + v] = hbits(P[(size_t)v * 512 + w]);
}

// ---------------------------------------------------------------- 4) seed zT block 0 (x hi), rows (n,w,l)
__global__ __launch_bounds__(512)
void seed_zT(const __half* __restrict__ Ah, __half* __restrict__ zT) {
    __shared__ uint32_t s32[32 * 257];      // [c][256 u32], pitch 257
    const int nl = blockIdx.x;              // n*13 + l
    const int n = nl / 13, l = nl - n * 13;
    const int tid = threadIdx.x;
    for (int i = tid; i < 32 * 256; i += 512) {
        int c = i >> 8, kk = i & 255;
        const uint32_t* pa = (const uint32_t*)(Ah + ((size_t)nl * 32 + c) * KA);
        s32[c * 257 + kk] = pa[kk];
    }
    __syncthreads();
    const int v = tid;
    uint32_t hi[16];
    #pragma unroll
    for (int i = 0; i < 16; i++) {
        uint32_t w0 = s32[(2*i) * 257 + (v >> 1)];
        uint32_t w1 = s32[(2*i+1) * 257 + (v >> 1)];
        uint16_t h0 = (v & 1) ? (uint16_t)(w0 >> 16) : (uint16_t)w0;
        uint16_t h1 = (v & 1) ? (uint16_t)(w1 >> 16) : (uint16_t)w1;
        hi[i] = (uint32_t)h0 | ((uint32_t)h1 << 16);
    }
    size_t gr = ((size_t)n * V_ + v) * L_ + l;      // row (n,v,l)
    char* dst = (char*)zT + gr * (ZTC * 2);
    #pragma unroll
    for (int i = 0; i < 4; i++)
        *(uint4*)(dst + i * 16) = *(uint4*)(hi + i * 4);
}

// ---------------------------------------------------------------- 5) GEMM1 (HMMA fp16) — R14 config (2 CTAs/SM)
#define BMg 128
#define BNg 128
#define BKg 64
#define NSTG 3
#define STG_A (BMg * BKg * 2)
#define STG_B (BNg * BKg * 2)
#define STG_BYTES (STG_A + STG_B)          // 32768
#define GEMM_SMEM (NSTG * STG_BYTES)       // 98304
#define KITERS 8                            // KA/BKg

__global__ __launch_bounds__(256, 2)
void mma_gemm(const __half* __restrict__ A, const __half* __restrict__ Bm,
              __half* __restrict__ zT) {
    extern __shared__ char smem[];
    const uint32_t sb = smem_u32(smem);
    const int tid = threadIdx.x;
    const int wid = tid >> 5, lane = tid & 31;
    const int bm = blockIdx.y * BMg;       // N-fastest launch for A L2 reuse
    const int bn = blockIdx.x * BNg;
    const int wm = wid & 3;
    const int wn = wid >> 2;

    float acc[2][8][4];
    #pragma unroll
    for (int i = 0; i < 2; i++)
        #pragma unroll
        for (int j = 0; j < 8; j++)
            #pragma unroll
            for (int q = 0; q < 4; q++) acc[i][j][q] = 0.f;

    auto load_stage = [&](int slot, int it) {
        const uint32_t abase = sb + slot * STG_BYTES;
        const uint32_t bbase = abase + STG_A;
        const __half* Ag = A + (size_t)bm * KA + it * BKg;
        const __half* Bg = Bm + (size_t)bn * KB + it * BKg;
        #pragma unroll
        for (int i = 0; i < 4; i++) {
            int c = tid + i * 256;
            int row = c >> 3, c16 = c & 7;
            uint32_t off = (uint32_t)(row * 128 + c16 * 16);
            cp_async16(abase + SW128(off), Ag + (size_t)row * KA + c16 * 8);
        }
        #pragma unroll
        for (int i = 0; i < 4; i++) {
            int c = tid + i * 256;
            int row = c >> 3, c16 = c & 7;
            uint32_t off = (uint32_t)(row * 128 + c16 * 16);
            cp_async16(bbase + SW128(off), Bg + (size_t)row * KB + c16 * 8);
        }
        asm volatile("cp.async.commit_group;" ::: "memory");
    };

    load_stage(0, 0);
    load_stage(1, 1);

    for (int it = 0; it < KITERS; it++) {
        if (it < KITERS - 1) asm volatile("cp.async.wait_group 1;" ::: "memory");
        else                 asm volatile("cp.async.wait_group 0;" ::: "memory");
        __syncthreads();
        if (it + 2 < KITERS) load_stage((it + 2) % NSTG, it + 2);

        const uint32_t abase = sb + (it % NSTG) * STG_BYTES;
        const uint32_t bbase = abase + STG_A;
        const int lrow = lane & 15;
        const int lkh  = (lane >> 4) << 3;

        #pragma unroll
        for (int ks = 0; ks < 4; ks++) {
            const int k0 = ks * 16;
            uint32_t a_regs[2][4];
            #pragma unroll
            for (int mf = 0; mf < 2; mf++) {
                int row = wm * 32 + mf * 16 + lrow;
                ldsm4(a_regs[mf], abase + SW128((uint32_t)(row * 128 + (k0 + lkh) * 2)));
            }
            uint32_t b_regs[4][4];
            #pragma unroll
            for (int nq = 0; nq < 4; nq++) {
                int row = wn * 64 + nq * 16 + lrow;
                ldsm4(b_regs[nq], bbase + SW128((uint32_t)(row * 128 + (k0 + lkh) * 2)));
            }
            #pragma unroll
            for (int mf = 0; mf < 2; mf++)
                #pragma unroll
                for (int nq = 0; nq < 4; nq++) {
                    mma16816(acc[mf][nq * 2 + 0], a_regs[mf], b_regs[nq][0], b_regs[nq][2]);
                    mma16816(acc[mf][nq * 2 + 1], a_regs[mf], b_regs[nq][1], b_regs[nq][3]);
                }
        }
    }
    __syncthreads();    // smem reuse below

    // epilogue: acc -> smem fp32 [128][129] -> zT fp16 hi, c-transposed, rows (n,w,l)
    float* s = (float*)smem;
    const int gid = lane >> 2, tig = lane & 3;
    #pragma unroll
    for (int mf = 0; mf < 2; mf++) {
        int r0 = wm * 32 + mf * 16 + gid;
        #pragma unroll
        for (int nf = 0; nf < 8; nf++) {
            int cc = wn * 64 + nf * 8 + tig * 2;
            float* d = acc[mf][nf];
            s[r0 * 129 + cc] = d[0];       s[r0 * 129 + cc + 1] = d[1];
            s[(r0 + 8) * 129 + cc] = d[2]; s[(r0 + 8) * 129 + cc + 1] = d[3];
        }
    }
    __syncthreads();

    const int p = bn >> 9;
    const int wbase = bn & 511;
    const int nlbase = bm >> 5;             // first of 4 (n,l) groups
    #pragma unroll
    for (int rep = 0; rep < 2; rep++) {
        int rw = tid + rep * 256;
        int nlg = rw >> 7, w = rw & 127;
        uint32_t hi[16];
        #pragma unroll
        for (int i = 0; i < 16; i++) {
            float v0 = s[(nlg * 32 + 2*i) * 129 + w];
            float v1 = s[(nlg * 32 + 2*i + 1) * 129 + w];
            hi[i] = (uint32_t)hbits(v0) | ((uint32_t)hbits(v1) << 16);
        }
        int nl = nlbase + nlg;
        int n = nl / 13, l = nl - n * 13;
        size_t gr = ((size_t)n * V_ + wbase + w) * L_ + l;
        char* dst = (char*)zT + gr * (ZTC * 2) + (p + 1) * 64;
        #pragma unroll
        for (int i = 0; i < 4; i++)
            *(uint4*)(dst + i * 16) = *(uint4*)(hi + i * 4);
    }
}

// ---------------------------------------------------------------- 6) W fp32 -> fp16
__global__ __launch_bounds__(256)
void build_W(const float* __restrict__ W, __half* __restrict__ Wh) {
    int idx = blockIdx.x * 256 + threadIdx.x;
    if (idx >= COUT * 224) return;
    ((uint16_t*)Wh)[idx] = hbits(W[idx]);
}

// ---------------------------------------------------------------- 7) mix GEMM (HMMA fp16), BM=256, 4-stage, fused output
#define MIX_BM 256
#define MIX_NSTG 4
#define MIX_WP 232                          // ws pitch (u16)
#define MIX_WBYTES (COUT * MIX_WP * 2)      // 29696
#define MIX_APITCH 80
#define MIX_ASTAGE (MIX_BM * MIX_APITCH)    // 20480
#define MIX_STG_TOT (MIX_NSTG * MIX_ASTAGE) // 81920
#define MIX_SMEM (MIX_WBYTES + MIX_STG_TOT) // 111616 (epilogue s2 66560 fits in stages)

__global__ __launch_bounds__(256, 2)
void mix_gemm(const __half* __restrict__ zT, const __half* __restrict__ Wh,
              const float* __restrict__ bias, float* __restrict__ out) {
    extern __shared__ char smem[];
    const uint32_t sb = smem_u32(smem);
    uint16_t* ws = (uint16_t*)smem;                        // [64][232]
    const uint32_t asb = sb + MIX_WBYTES;
    const int tid = threadIdx.x;
    const int wid = tid >> 5, lane = tid & 31;
    const int bm = blockIdx.x * MIX_BM;                    // 1664 tiles; 26 per n
    const int wm = wid & 3, wn = wid >> 2;                 // warp tile 64 rows x 32 cols

    for (int i = tid; i < COUT * 112; i += 256) {
        int o = i / 112, kk = (i % 112) * 2;
        *(uint32_t*)(ws + o * MIX_WP + kk) =
            *(const uint32_t*)((const uint16_t*)Wh + o * 224 + kk);
    }

    float acc[4][4][4];
    #pragma unroll
    for (int i = 0; i < 4; i++)
        #pragma unroll
        for (int j = 0; j < 4; j++)
            #pragma unroll
            for (int q = 0; q < 4; q++) acc[i][j][q] = 0.f;

    auto load_stage = [&](int slot, int chunk) {
        const uint32_t base = asb + slot * MIX_ASTAGE;
        const int ac = chunk * 32;
        #pragma unroll
        for (int i = 0; i < 4; i++) {                      // 1024 x 16B
            int c = tid + i * 256;
            int row = c >> 2, c16 = c & 3;
            cp_async16(base + row * MIX_APITCH + c16 * 16,
                       zT + ((size_t)bm + row) * ZTC + ac + c16 * 8);
        }
        asm volatile("cp.async.commit_group;" ::: "memory");
    };

    load_stage(0, 0);
    load_stage(1, 1);
    load_stage(2, 2);
    __syncthreads();    // covers ws preload too

    const int lrow = lane & 15;
    const int lkh  = (lane >> 4) << 3;
    const int og   = lane >> 2;
    const int kq   = (lane & 3) * 2;

    for (int it = 0; it < 7; it++) {
        int rem = 6 - it;
        if (rem >= 2)      asm volatile("cp.async.wait_group 2;" ::: "memory");
        else if (rem == 1) asm volatile("cp.async.wait_group 1;" ::: "memory");
        else               asm volatile("cp.async.wait_group 0;" ::: "memory");
        __syncthreads();
        if (it + 3 < 7) load_stage((it + 3) % MIX_NSTG, it + 3);

        const uint32_t abase = asb + (it % MIX_NSTG) * MIX_ASTAGE;
        const int bc = it * 32;

        #pragma unroll
        for (int ks = 0; ks < 2; ks++) {
            uint32_t a_regs[4][4];
            #pragma unroll
            for (int mf = 0; mf < 4; mf++) {
                int row = wm * 64 + mf * 16 + lrow;
                ldsm4(a_regs[mf], abase + row * MIX_APITCH + (ks * 16 + lkh) * 2);
            }
            #pragma unroll
            for (int nq = 0; nq < 4; nq++) {
                int o = wn * 32 + nq * 8 + og;
                int k = bc + ks * 16 + kq;
                uint32_t b0 = *(uint32_t*)(ws + o * MIX_WP + k);
                uint32_t b1 = *(uint32_t*)(ws + o * MIX_WP + k + 8);
                #pragma unroll
                for (int mf = 0; mf < 4; mf++)
                    mma16816(acc[mf][nq], a_regs[mf], b0, b1);
            }
        }
    }
    __syncthreads();    // smem reuse as s2

    // epilogue: stage [o][row] (pitch 260), then coalesced direct out writes
    float* s2 = (float*)(smem + MIX_WBYTES);
    const int gid = lane >> 2, tig = lane & 3;
    #pragma unroll
    for (int mf = 0; mf < 4; mf++) {
        int r0 = wm * 64 + mf * 16 + gid;
        #pragma unroll
        for (int nq = 0; nq < 4; nq++) {
            int o = wn * 32 + nq * 8 + tig * 2;
            float* d = acc[mf][nq];
            s2[o * 260 + r0] = d[0];       s2[(o + 1) * 260 + r0] = d[1];
            s2[o * 260 + r0 + 8] = d[2];   s2[(o + 1) * 260 + r0 + 8] = d[3];
        }
    }
    __syncthreads();

    // rows = contiguous (w,l) span within one n (6656 = 26*256)
    const int n = bm / VL;
    const int rowbase = bm - n * VL;
    #pragma unroll
    for (int i = 0; i < 16; i++) {
        int idx = tid + i * 256;           // 4096 float4s = 64 o x 256 floats
        int o = idx >> 6, q = idx & 63;
        float4 v = *(float4*)(s2 + o * 260 + q * 4);
        float bo = bias[o];
        v.x += bo; v.y += bo; v.z += bo; v.w += bo;
        *(float4*)(out + ((size_t)n * COUT + o) * VL + rowbase + q * 4) = v;
    }
}

// ---------------------------------------------------------------- launcher (R12 multi-stream DAG)
extern "C" void kernel_launch(void* const* d_in, const int* in_sizes, int n_in,
                              void* d_out, int out_size) {
    const float* x  = (const float*)d_in[0];
    const float* a0 = (const float*)d_in[1];
    const float* a1 = (const float*)d_in[2];
    const float* a2 = (const float*)d_in[3];
    const float* W  = (const float*)d_in[4];
    const float* b  = (const float*)d_in[5];
    float* out = (float*)d_out;

    float* pw;
    __half *Ah, *Bh, *zT, *Wh;
    cudaGetSymbolAddress((void**)&pw,  g_pow);
    cudaGetSymbolAddress((void**)&Ah,  g_Ah);
    cudaGetSymbolAddress((void**)&Bh,  g_Bh);
    cudaGetSymbolAddress((void**)&zT,  g_zT);
    cudaGetSymbolAddress((void**)&Wh,  g_Wh);

    cudaFuncSetAttribute(mma_gemm, cudaFuncAttributeMaxDynamicSharedMemorySize, GEMM_SMEM);
    cudaFuncSetAttribute(mix_gemm, cudaFuncAttributeMaxDynamicSharedMemorySize, MIX_SMEM);

    // Host-side stream/event objects, created once (no device memory involved).
    static cudaStream_t s2 = nullptr, s3 = nullptr;
    static cudaEvent_t evRoot = nullptr, evA = nullptr, evB = nullptr,
                       evS = nullptr, evW = nullptr;
    if (s2 == nullptr) {
        cudaStreamCreateWithFlags(&s2, cudaStreamNonBlocking);
        cudaStreamCreateWithFlags(&s3, cudaStreamNonBlocking);
        cudaEventCreateWithFlags(&evRoot, cudaEventDisableTiming);
        cudaEventCreateWithFlags(&evA, cudaEventDisableTiming);
        cudaEventCreateWithFlags(&evB, cudaEventDisableTiming);
        cudaEventCreateWithFlags(&evS, cudaEventDisableTiming);
        cudaEventCreateWithFlags(&evW, cudaEventDisableTiming);
    }

    // fork
    cudaEventRecord(evRoot, 0);
    cudaStreamWaitEvent(s2, evRoot, 0);
    cudaStreamWaitEvent(s3, evRoot, 0);

    // side branch s2: supports -> a^2 -> Bh, plus Wh
    pow_kernel<<<dim3(8, 8, 3), 256, 0, s2>>>(a0, a1, a2, pw);
    build_B<<<(NB * 512) / 256, 256, 0, s2>>>(a0, a1, a2, pw, Bh);
    cudaEventRecord(evB, s2);
    build_W<<<(COUT * 224 + 255) / 256, 256, 0, s2>>>(W, Wh);
    cudaEventRecord(evW, s2);

    // main stream: x -> Ah
    build_A<<<B_ * C_, 256>>>(x, Ah);
    cudaEventRecord(evA, 0);

    // side branch s3: seed zT block 0 (runs concurrently with GEMM1)
    cudaStreamWaitEvent(s3, evA, 0);
    seed_zT<<<B_ * L_, 512, 0, s3>>>(Ah, zT);
    cudaEventRecord(evS, s3);

    // main stream: GEMM1 (needs Ah in-stream + Bh via event)
    cudaStreamWaitEvent(0, evB, 0);
    mma_gemm<<<dim3(NB / BNg, M_ROWS / BMg), 256, GEMM_SMEM>>>(Ah, Bh, zT);

    // join: mix needs zT block 0 (seed) + Wh; writes out directly
    cudaStreamWaitEvent(0, evS, 0);
    cudaStreamWaitEvent(0, evW, 0);
    mix_gemm<<<ZROWS / MIX_BM, 256, MIX_SMEM>>>(zT, Wh, b, out);
}

// round 17
// speedup vs baseline: 1.1589x; 1.0564x over previous
#include <cuda_runtime.h>
#include <cuda_fp16.h>
#include <cstdint>

// ---------------------------------------------------------------- constants
#define B_    64
#define C_    32
#define V_    512
#define L_    13
#define COUT  64
#define M_ROWS 26624            // B_*C_*L_  GEMM1 rows ordered (n,l,c)
#define NB    3072              // 6 support-powers * 512
#define KA    512               // A cols: xh only
#define KB    512               // B cols: ah only
#define ZROWS 425984            // 64 n * 6656 (w,l)  — zT rows ordered (n,w,l)
#define ZTC   224               // zT cols: hi only (7 chan blocks x 32)
#define VL    6656              // 512*13

// ---------------------------------------------------------------- scratch
__device__ __half g_Ah[(size_t)M_ROWS * KA];      // 27.3 MB
__device__ __half g_Bh[(size_t)NB * KB];          // 3.1 MB
__device__ __half g_zT[(size_t)ZROWS * ZTC];      // 190.8 MB
__device__ __half g_Wh[COUT * 224];
__device__ float  g_pow[3 * V_ * V_];

// ---------------------------------------------------------------- utils
__device__ __forceinline__ uint32_t smem_u32(const void* p) {
    uint32_t a;
    asm("{ .reg .u64 t; cvta.to.shared.u64 t, %1; cvt.u32.u64 %0, t; }" : "=r"(a) : "l"(p));
    return a;
}
__device__ __forceinline__ void cp_async16(uint32_t s, const void* g) {
    asm volatile("cp.async.cg.shared.global [%0], [%1], 16;" :: "r"(s), "l"(g));
}
__device__ __forceinline__ void ldsm4(uint32_t* r, uint32_t addr) {
    asm volatile("ldmatrix.sync.aligned.m8n8.x4.shared.b16 {%0,%1,%2,%3}, [%4];"
                 : "=r"(r[0]), "=r"(r[1]), "=r"(r[2]), "=r"(r[3]) : "r"(addr));
}
__device__ __forceinline__ void mma16816(float* d, const uint32_t* a, uint32_t b0, uint32_t b1) {
    asm volatile(
        "mma.sync.aligned.m16n8k16.row.col.f32.f16.f16.f32 "
        "{%0,%1,%2,%3}, {%4,%5,%6,%7}, {%8,%9}, {%0,%1,%2,%3};"
        : "+f"(d[0]), "+f"(d[1]), "+f"(d[2]), "+f"(d[3])
        : "r"(a[0]), "r"(a[1]), "r"(a[2]), "r"(a[3]), "r"(b0), "r"(b1));
}
#define SW128(off) ((off) ^ (((off) >> 3) & 0x70))

__device__ __forceinline__ uint16_t hbits(float f) {
    __half h = __float2half_rn(f);
    return *reinterpret_cast<uint16_t*>(&h);
}

// ---------------------------------------------------------------- 1) a^2 (fp32)
__global__ __launch_bounds__(256)
void pow_kernel(const float* __restrict__ a0, const float* __restrict__ a1,
                const float* __restrict__ a2, float* __restrict__ out) {
    const float* A = (blockIdx.z == 0) ? a0 : (blockIdx.z == 1 ? a1 : a2);
    float* Cc = out + (size_t)blockIdx.z * V_ * V_;
    __shared__ float As[16][64];
    __shared__ float Bs[16][68];
    const int tid = threadIdx.x;
    const int bm = blockIdx.y * 64, bn = blockIdx.x * 64;
    const int tx = tid & 15, ty = tid >> 4;
    float acc[4][4] = {};
    for (int kb = 0; kb < 512; kb += 16) {
        float4 va = *(const float4*)(A + (size_t)(bm + (tid >> 2)) * 512 + kb + (tid & 3) * 4);
        As[(tid & 3) * 4 + 0][tid >> 2] = va.x;
        As[(tid & 3) * 4 + 1][tid >> 2] = va.y;
        As[(tid & 3) * 4 + 2][tid >> 2] = va.z;
        As[(tid & 3) * 4 + 3][tid >> 2] = va.w;
        *(float4*)&Bs[tid >> 4][(tid & 15) * 4] =
            *(const float4*)(A + (size_t)(kb + (tid >> 4)) * 512 + bn + (tid & 15) * 4);
        __syncthreads();
        #pragma unroll
        for (int k = 0; k < 16; k++) {
            float wf[4], hf[4];
            #pragma unroll
            for (int i = 0; i < 4; i++) wf[i] = As[k][ty * 4 + i];
            #pragma unroll
            for (int j = 0; j < 4; j++) hf[j] = Bs[k][tx * 4 + j];
            #pragma unroll
            for (int i = 0; i < 4; i++)
                #pragma unroll
                for (int j = 0; j < 4; j++) acc[i][j] = fmaf(wf[i], hf[j], acc[i][j]);
        }
        __syncthreads();
    }
    #pragma unroll
    for (int i = 0; i < 4; i++)
        #pragma unroll
        for (int j = 0; j < 4; j++)
            Cc[(size_t)(bm + ty * 4 + i) * 512 + bn + tx * 4 + j] = acc[i][j];
}

// ---------------------------------------------------------------- 2) A rows (n,l,c): xh (float4 loads, u32 stores)
__global__ __launch_bounds__(256)
void build_A(const float* __restrict__ x, __half* __restrict__ Ah) {
    __shared__ float s[V_ * L_];
    const int nc = blockIdx.x;              // n*32 + c
    const int n = nc >> 5, c = nc & 31;
    const int tid = threadIdx.x;
    const float4* slab4 = (const float4*)(x + (size_t)nc * (V_ * L_));
    for (int i = tid; i < (V_ * L_) / 4; i += 256)
        *(float4*)&s[i * 4] = slab4[i];
    __syncthreads();
    for (int e = tid; e < (V_ / 2) * L_; e += 256) {
        int l = e / 256, v2 = (e & 255) * 2;
        float v0 = s[v2 * L_ + l];
        float v1 = s[(v2 + 1) * L_ + l];
        uint32_t pk = (uint32_t)hbits(v0) | ((uint32_t)hbits(v1) << 16);
        size_t m = ((size_t)n * L_ + l) * 32 + c;
        *(uint32_t*)((uint16_t*)Ah + m * KA + v2) = pk;
    }
}

// ---------------------------------------------------------------- 3) B (hi only) + W fp16 (merged)
__global__ __launch_bounds__(256)
void build_B(const float* __restrict__ a0, const float* __restrict__ a1,
             const float* __restrict__ a2, const float* __restrict__ pw,
             const float* __restrict__ W,
             __half* __restrict__ Bh, __half* __restrict__ Wh) {
    int idx = blockIdx.x * 256 + threadIdx.x;
    if (idx < NB * 512) {
        int v = idx & 511;
        int j = idx >> 9;                // B row: p*512 + w
        int p = j >> 9;
        int w = j & 511;
        const float* P = (p & 1) ? (pw + (size_t)(p >> 1) * V_ * V_)
                                 : (p == 0 ? a0 : (p == 2 ? a1 : a2));
        ((uint16_t*)Bh)[(size_t)j * KB + v] = hbits(P[(size_t)v * 512 + w]);
    } else {
        int i2 = idx - NB * 512;
        if (i2 < COUT * 224)
            ((uint16_t*)Wh)[i2] = hbits(W[i2]);
    }
}

// ---------------------------------------------------------------- 4) seed zT block 0 (x hi), rows (n,w,l)
__global__ __launch_bounds__(512)
void seed_zT(const __half* __restrict__ Ah, __half* __restrict__ zT) {
    __shared__ uint32_t s32[32 * 257];      // [c][256 u32], pitch 257
    const int nl = blockIdx.x;              // n*13 + l
    const int n = nl / 13, l = nl - n * 13;
    const int tid = threadIdx.x;
    for (int i = tid; i < 32 * 256; i += 512) {
        int c = i >> 8, kk = i & 255;
        const uint32_t* pa = (const uint32_t*)(Ah + ((size_t)nl * 32 + c) * KA);
        s32[c * 257 + kk] = pa[kk];
    }
    __syncthreads();
    const int v = tid;
    uint32_t hi[16];
    #pragma unroll
    for (int i = 0; i < 16; i++) {
        uint32_t w0 = s32[(2*i) * 257 + (v >> 1)];
        uint32_t w1 = s32[(2*i+1) * 257 + (v >> 1)];
        uint16_t h0 = (v & 1) ? (uint16_t)(w0 >> 16) : (uint16_t)w0;
        uint16_t h1 = (v & 1) ? (uint16_t)(w1 >> 16) : (uint16_t)w1;
        hi[i] = (uint32_t)h0 | ((uint32_t)h1 << 16);
    }
    size_t gr = ((size_t)n * V_ + v) * L_ + l;      // row (n,v,l)
    char* dst = (char*)zT + gr * (ZTC * 2);
    #pragma unroll
    for (int i = 0; i < 4; i++)
        *(uint4*)(dst + i * 16) = *(uint4*)(hi + i * 4);
}

// ---------------------------------------------------------------- 5) GEMM1 (HMMA fp16), 2 CTAs/SM, fp16 epilogue staging
#define BMg 128
#define BNg 128
#define BKg 64
#define NSTG 3
#define STG_A (BMg * BKg * 2)
#define STG_B (BNg * BKg * 2)
#define STG_BYTES (STG_A + STG_B)          // 32768
#define GEMM_SMEM (NSTG * STG_BYTES)       // 98304
#define KITERS 8                            // KA/BKg
#define EPI_P 130                           // u16 staging pitch

__global__ __launch_bounds__(256, 2)
void mma_gemm(const __half* __restrict__ A, const __half* __restrict__ Bm,
              __half* __restrict__ zT) {
    extern __shared__ char smem[];
    const uint32_t sb = smem_u32(smem);
    const int tid = threadIdx.x;
    const int wid = tid >> 5, lane = tid & 31;
    const int bm = blockIdx.y * BMg;       // N-fastest launch for A L2 reuse
    const int bn = blockIdx.x * BNg;
    const int wm = wid & 3;
    const int wn = wid >> 2;

    float acc[2][8][4];
    #pragma unroll
    for (int i = 0; i < 2; i++)
        #pragma unroll
        for (int j = 0; j < 8; j++)
            #pragma unroll
            for (int q = 0; q < 4; q++) acc[i][j][q] = 0.f;

    auto load_stage = [&](int slot, int it) {
        const uint32_t abase = sb + slot * STG_BYTES;
        const uint32_t bbase = abase + STG_A;
        const __half* Ag = A + (size_t)bm * KA + it * BKg;
        const __half* Bg = Bm + (size_t)bn * KB + it * BKg;
        #pragma unroll
        for (int i = 0; i < 4; i++) {
            int c = tid + i * 256;
            int row = c >> 3, c16 = c & 7;
            uint32_t off = (uint32_t)(row * 128 + c16 * 16);
            cp_async16(abase + SW128(off), Ag + (size_t)row * KA + c16 * 8);
        }
        #pragma unroll
        for (int i = 0; i < 4; i++) {
            int c = tid + i * 256;
            int row = c >> 3, c16 = c & 7;
            uint32_t off = (uint32_t)(row * 128 + c16 * 16);
            cp_async16(bbase + SW128(off), Bg + (size_t)row * KB + c16 * 8);
        }
        asm volatile("cp.async.commit_group;" ::: "memory");
    };

    load_stage(0, 0);
    load_stage(1, 1);

    for (int it = 0; it < KITERS; it++) {
        if (it < KITERS - 1) asm volatile("cp.async.wait_group 1;" ::: "memory");
        else                 asm volatile("cp.async.wait_group 0;" ::: "memory");
        __syncthreads();
        if (it + 2 < KITERS) load_stage((it + 2) % NSTG, it + 2);

        const uint32_t abase = sb + (it % NSTG) * STG_BYTES;
        const uint32_t bbase = abase + STG_A;
        const int lrow = lane & 15;
        const int lkh  = (lane >> 4) << 3;

        #pragma unroll
        for (int ks = 0; ks < 4; ks++) {
            const int k0 = ks * 16;
            uint32_t a_regs[2][4];
            #pragma unroll
            for (int mf = 0; mf < 2; mf++) {
                int row = wm * 32 + mf * 16 + lrow;
                ldsm4(a_regs[mf], abase + SW128((uint32_t)(row * 128 + (k0 + lkh) * 2)));
            }
            uint32_t b_regs[4][4];
            #pragma unroll
            for (int nq = 0; nq < 4; nq++) {
                int row = wn * 64 + nq * 16 + lrow;
                ldsm4(b_regs[nq], bbase + SW128((uint32_t)(row * 128 + (k0 + lkh) * 2)));
            }
            #pragma unroll
            for (int mf = 0; mf < 2; mf++)
                #pragma unroll
                for (int nq = 0; nq < 4; nq++) {
                    mma16816(acc[mf][nq * 2 + 0], a_regs[mf], b_regs[nq][0], b_regs[nq][2]);
                    mma16816(acc[mf][nq * 2 + 1], a_regs[mf], b_regs[nq][1], b_regs[nq][3]);
                }
        }
    }
    __syncthreads();    // smem reuse below

    // epilogue: acc -> smem fp16 [128][130] -> zT fp16 hi, c-transposed, rows (n,w,l)
    uint16_t* s16 = (uint16_t*)smem;        // 128*130*2 = 33280 B
    const int gid = lane >> 2, tig = lane & 3;
    #pragma unroll
    for (int mf = 0; mf < 2; mf++) {
        int r0 = wm * 32 + mf * 16 + gid;
        #pragma unroll
        for (int nf = 0; nf < 8; nf++) {
            int cc = wn * 64 + nf * 8 + tig * 2;
            float* d = acc[mf][nf];
            *(uint32_t*)&s16[r0 * EPI_P + cc] =
                (uint32_t)hbits(d[0]) | ((uint32_t)hbits(d[1]) << 16);
            *(uint32_t*)&s16[(r0 + 8) * EPI_P + cc] =
                (uint32_t)hbits(d[2]) | ((uint32_t)hbits(d[3]) << 16);
        }
    }
    __syncthreads();

    const int p = bn >> 9;
    const int wbase = bn & 511;
    const int nlbase = bm >> 5;             // first of 4 (n,l) groups
    #pragma unroll
    for (int rep = 0; rep < 2; rep++) {
        int rw = tid + rep * 256;
        int nlg = rw >> 7, w = rw & 127;
        uint32_t hi[16];
        #pragma unroll
        for (int i = 0; i < 16; i++) {
            uint32_t h0 = s16[(nlg * 32 + 2*i)     * EPI_P + w];
            uint32_t h1 = s16[(nlg * 32 + 2*i + 1) * EPI_P + w];
            hi[i] = h0 | (h1 << 16);
        }
        int nl = nlbase + nlg;
        int n = nl / 13, l = nl - n * 13;
        size_t gr = ((size_t)n * V_ + wbase + w) * L_ + l;
        char* dst = (char*)zT + gr * (ZTC * 2) + (p + 1) * 64;
        #pragma unroll
        for (int i = 0; i < 4; i++)
            *(uint4*)(dst + i * 16) = *(uint4*)(hi + i * 4);
    }
}

// ---------------------------------------------------------------- 6) mix GEMM (HMMA fp16), BM=256, 4-stage, fused output
#define MIX_BM 256
#define MIX_NSTG 4
#define MIX_WP 232                          // ws pitch (u16)
#define MIX_WBYTES (COUT * MIX_WP * 2)      // 29696
#define MIX_APITCH 80
#define MIX_ASTAGE (MIX_BM * MIX_APITCH)    // 20480
#define MIX_STG_TOT (MIX_NSTG * MIX_ASTAGE) // 81920
#define MIX_SMEM (MIX_WBYTES + MIX_STG_TOT) // 111616 (epilogue s2 66560 fits in stages)

__global__ __launch_bounds__(256, 2)
void mix_gemm(const __half* __restrict__ zT, const __half* __restrict__ Wh,
              const float* __restrict__ bias, float* __restrict__ out) {
    extern __shared__ char smem[];
    const uint32_t sb = smem_u32(smem);
    uint16_t* ws = (uint16_t*)smem;                        // [64][232]
    const uint32_t asb = sb + MIX_WBYTES;
    const int tid = threadIdx.x;
    const int wid = tid >> 5, lane = tid & 31;
    const int bm = blockIdx.x * MIX_BM;                    // 1664 tiles; 26 per n
    const int wm = wid & 3, wn = wid >> 2;                 // warp tile 64 rows x 32 cols

    for (int i = tid; i < COUT * 112; i += 256) {
        int o = i / 112, kk = (i % 112) * 2;
        *(uint32_t*)(ws + o * MIX_WP + kk) =
            *(const uint32_t*)((const uint16_t*)Wh + o * 224 + kk);
    }

    float acc[4][4][4];
    #pragma unroll
    for (int i = 0; i < 4; i++)
        #pragma unroll
        for (int j = 0; j < 4; j++)
            #pragma unroll
            for (int q = 0; q < 4; q++) acc[i][j][q] = 0.f;

    auto load_stage = [&](int slot, int chunk) {
        const uint32_t base = asb + slot * MIX_ASTAGE;
        const int ac = chunk * 32;
        #pragma unroll
        for (int i = 0; i < 4; i++) {                      // 1024 x 16B
            int c = tid + i * 256;
            int row = c >> 2, c16 = c & 3;
            cp_async16(base + row * MIX_APITCH + c16 * 16,
                       zT + ((size_t)bm + row) * ZTC + ac + c16 * 8);
        }
        asm volatile("cp.async.commit_group;" ::: "memory");
    };

    load_stage(0, 0);
    load_stage(1, 1);
    load_stage(2, 2);
    __syncthreads();    // covers ws preload too

    const int lrow = lane & 15;
    const int lkh  = (lane >> 4) << 3;
    const int og   = lane >> 2;
    const int kq   = (lane & 3) * 2;

    for (int it = 0; it < 7; it++) {
        int rem = 6 - it;
        if (rem >= 2)      asm volatile("cp.async.wait_group 2;" ::: "memory");
        else if (rem == 1) asm volatile("cp.async.wait_group 1;" ::: "memory");
        else               asm volatile("cp.async.wait_group 0;" ::: "memory");
        __syncthreads();
        if (it + 3 < 7) load_stage((it + 3) % MIX_NSTG, it + 3);

        const uint32_t abase = asb + (it % MIX_NSTG) * MIX_ASTAGE;
        const int bc = it * 32;

        #pragma unroll
        for (int ks = 0; ks < 2; ks++) {
            uint32_t a_regs[4][4];
            #pragma unroll
            for (int mf = 0; mf < 4; mf++) {
                int row = wm * 64 + mf * 16 + lrow;
                ldsm4(a_regs[mf], abase + row * MIX_APITCH + (ks * 16 + lkh) * 2);
            }
            #pragma unroll
            for (int nq = 0; nq < 4; nq++) {
                int o = wn * 32 + nq * 8 + og;
                int k = bc + ks * 16 + kq;
                uint32_t b0 = *(uint32_t*)(ws + o * MIX_WP + k);
                uint32_t b1 = *(uint32_t*)(ws + o * MIX_WP + k + 8);
                #pragma unroll
                for (int mf = 0; mf < 4; mf++)
                    mma16816(acc[mf][nq], a_regs[mf], b0, b1);
            }
        }
    }
    __syncthreads();    // smem reuse as s2

    // epilogue: stage [o][row] (pitch 260), then coalesced streaming out writes
    float* s2 = (float*)(smem + MIX_WBYTES);
    const int gid = lane >> 2, tig = lane & 3;
    #pragma unroll
    for (int mf = 0; mf < 4; mf++) {
        int r0 = wm * 64 + mf * 16 + gid;
        #pragma unroll
        for (int nq = 0; nq < 4; nq++) {
            int o = wn * 32 + nq * 8 + tig * 2;
            float* d = acc[mf][nq];
            s2[o * 260 + r0] = d[0];       s2[(o + 1) * 260 + r0] = d[1];
            s2[o * 260 + r0 + 8] = d[2];   s2[(o + 1) * 260 + r0 + 8] = d[3];
        }
    }
    __syncthreads();

    // rows = contiguous (w,l) span within one n (6656 = 26*256)
    const int n = bm / VL;
    const int rowbase = bm - n * VL;
    #pragma unroll
    for (int i = 0; i < 16; i++) {
        int idx = tid + i * 256;           // 4096 float4s = 64 o x 256 floats
        int o = idx >> 6, q = idx & 63;
        float4 v = *(float4*)(s2 + o * 260 + q * 4);
        float bo = bias[o];
        v.x += bo; v.y += bo; v.z += bo; v.w += bo;
        __stcs((float4*)(out + ((size_t)n * COUT + o) * VL + rowbase + q * 4), v);
    }
}

// ---------------------------------------------------------------- launcher (multi-stream DAG)
extern "C" void kernel_launch(void* const* d_in, const int* in_sizes, int n_in,
                              void* d_out, int out_size) {
    const float* x  = (const float*)d_in[0];
    const float* a0 = (const float*)d_in[1];
    const float* a1 = (const float*)d_in[2];
    const float* a2 = (const float*)d_in[3];
    const float* W  = (const float*)d_in[4];
    const float* b  = (const float*)d_in[5];
    float* out = (float*)d_out;

    float* pw;
    __half *Ah, *Bh, *zT, *Wh;
    cudaGetSymbolAddress((void**)&pw,  g_pow);
    cudaGetSymbolAddress((void**)&Ah,  g_Ah);
    cudaGetSymbolAddress((void**)&Bh,  g_Bh);
    cudaGetSymbolAddress((void**)&zT,  g_zT);
    cudaGetSymbolAddress((void**)&Wh,  g_Wh);

    cudaFuncSetAttribute(mma_gemm, cudaFuncAttributeMaxDynamicSharedMemorySize, GEMM_SMEM);
    cudaFuncSetAttribute(mix_gemm, cudaFuncAttributeMaxDynamicSharedMemorySize, MIX_SMEM);

    // Host-side stream/event objects, created once (no device memory involved).
    static cudaStream_t s2 = nullptr, s3 = nullptr;
    static cudaEvent_t evRoot = nullptr, evA = nullptr, evB = nullptr, evS = nullptr;
    if (s2 == nullptr) {
        cudaStreamCreateWithFlags(&s2, cudaStreamNonBlocking);
        cudaStreamCreateWithFlags(&s3, cudaStreamNonBlocking);
        cudaEventCreateWithFlags(&evRoot, cudaEventDisableTiming);
        cudaEventCreateWithFlags(&evA, cudaEventDisableTiming);
        cudaEventCreateWithFlags(&evB, cudaEventDisableTiming);
        cudaEventCreateWithFlags(&evS, cudaEventDisableTiming);
    }

    // fork
    cudaEventRecord(evRoot, 0);
    cudaStreamWaitEvent(s2, evRoot, 0);
    cudaStreamWaitEvent(s3, evRoot, 0);

    // side branch s2: supports -> a^2 -> (Bh + Wh merged)
    pow_kernel<<<dim3(8, 8, 3), 256, 0, s2>>>(a0, a1, a2, pw);
    build_B<<<(NB * 512 + COUT * 224 + 255) / 256, 256, 0, s2>>>(a0, a1, a2, pw, W, Bh, Wh);
    cudaEventRecord(evB, s2);

    // main stream: x -> Ah
    build_A<<<B_ * C_, 256>>>(x, Ah);
    cudaEventRecord(evA, 0);

    // side branch s3: seed zT block 0 (runs concurrently with GEMM1)
    cudaStreamWaitEvent(s3, evA, 0);
    seed_zT<<<B_ * L_, 512, 0, s3>>>(Ah, zT);
    cudaEventRecord(evS, s3);

    // main stream: GEMM1 (needs Ah in-stream + Bh/Wh via event)
    cudaStreamWaitEvent(0, evB, 0);
    mma_gemm<<<dim3(NB / BNg, M_ROWS / BMg), 256, GEMM_SMEM>>>(Ah, Bh, zT);

    // join: mix needs zT block 0 (seed); Wh ready via evB (already waited)
    cudaStreamWaitEvent(0, evS, 0);
    mix_gemm<<<ZROWS / MIX_BM, 256, MIX_SMEM>>>(zT, Wh, b, out);
}